// round 1
// baseline (speedup 1.0000x reference)
#include <cuda_runtime.h>
#include <math.h>

#define TT 128
#define BB 512
#define DD 300
#define HH 512
#define G3 1536

// Scratch: gi = x@Wih^T + bih for all timesteps, per direction; seq = per-layer
// hidden states for all timesteps, per direction (overwritten layer by layer).
__device__ float g_gi[2][(size_t)TT * BB * G3];   // 2 x 402 MB
__device__ float g_seq[2][(size_t)TT * BB * HH];  // 2 x 134 MB

__device__ __forceinline__ float sigmoidf_(float x) { return 1.f / (1.f + expf(-x)); }

// ---------------------------------------------------------------------------
// gi GEMM: C[t*B+b, n] = sum_k A[t*B+b, k] * W[n, k] + bias[n]
// A is input_sequence (layer 0; dir 1 reads reversed time) or g_seq[dir].
// Tiles: 64x64, K-tile 16, 256 threads, 4x4 per thread.
// ---------------------------------------------------------------------------
__global__ __launch_bounds__(256) void gi_gemm(
    const float* __restrict__ x, int K, int is_layer0,
    const float* __restrict__ Wf, const float* __restrict__ Wb,
    const float* __restrict__ bf, const float* __restrict__ bb)
{
    __shared__ float As[16][66];
    __shared__ float Bs[16][66];

    const int dir = blockIdx.z;
    const float* W    = dir ? Wb : Wf;
    const float* bias = dir ? bb : bf;
    const int n0 = blockIdx.x * 64;
    const int m0 = blockIdx.y * 64;
    const int t = m0 / BB;           // 64 | 512, so t constant per tile
    const int brow0 = m0 % BB;

    const float* A;
    if (is_layer0) {
        const int tt = dir ? (TT - 1 - t) : t;
        A = x + ((size_t)tt * BB + brow0) * K;
    } else {
        A = &g_seq[dir][((size_t)t * BB + brow0) * HH];
    }
    float* C = &g_gi[dir][(size_t)m0 * G3];

    const int tid = threadIdx.x;
    const int tx = tid & 15, ty = tid >> 4;

    float acc[4][4];
    #pragma unroll
    for (int i = 0; i < 4; i++)
        #pragma unroll
        for (int j = 0; j < 4; j++) acc[i][j] = 0.f;

    for (int k0 = 0; k0 < K; k0 += 16) {
        #pragma unroll
        for (int i = 0; i < 4; i++) {
            const int e = tid + i * 256;
            const int kk = e & 15, mm = e >> 4;
            const int k = k0 + kk;
            As[kk][mm] = (k < K) ? A[(size_t)mm * K + k] : 0.f;
            Bs[kk][mm] = (k < K) ? W[(size_t)(n0 + mm) * K + k] : 0.f;
        }
        __syncthreads();
        #pragma unroll
        for (int kk = 0; kk < 16; kk++) {
            float a[4], b[4];
            #pragma unroll
            for (int i = 0; i < 4; i++) a[i] = As[kk][ty * 4 + i];
            #pragma unroll
            for (int j = 0; j < 4; j++) b[j] = Bs[kk][tx * 4 + j];
            #pragma unroll
            for (int i = 0; i < 4; i++)
                #pragma unroll
                for (int j = 0; j < 4; j++)
                    acc[i][j] += a[i] * b[j];
        }
        __syncthreads();
    }

    #pragma unroll
    for (int i = 0; i < 4; i++) {
        const int m = ty * 4 + i;
        #pragma unroll
        for (int j = 0; j < 4; j++) {
            const int n = n0 + tx * 4 + j;
            C[(size_t)m * G3 + n] = acc[i][j] + bias[n];
        }
    }
}

// ---------------------------------------------------------------------------
// Fused recurrent step: gh = h_{t-1} @ Whh^T (3 gates) + gate math.
// Reads g_seq[dir] at t-1, g_gi[dir] at t; writes g_seq[dir] at t.
// Grid: (H/64, B/64, 2). Each thread: 4x4 outputs x 3 gate accumulators.
// ---------------------------------------------------------------------------
__global__ __launch_bounds__(256) void gru_step(
    int t,
    const float* __restrict__ Whhf, const float* __restrict__ Whhb,
    const float* __restrict__ bhf,  const float* __restrict__ bhb)
{
    __shared__ float As[16][66];
    __shared__ float Bs[3][16][66];

    const int dir = blockIdx.z;
    const float* Whh = dir ? Whhb : Whhf;
    const float* bhh = dir ? bhb : bhf;
    const int n0 = blockIdx.x * 64;   // over H
    const int m0 = blockIdx.y * 64;   // over B

    const float* gi   = &g_gi[dir][((size_t)t * BB + m0) * G3];
    float* hout       = &g_seq[dir][((size_t)t * BB + m0) * HH];
    const float* hprev = (t > 0) ? &g_seq[dir][((size_t)(t - 1) * BB + m0) * HH] : nullptr;

    const int tid = threadIdx.x;
    const int tx = tid & 15, ty = tid >> 4;

    float ar[4][4], az[4][4], an[4][4];
    #pragma unroll
    for (int i = 0; i < 4; i++)
        #pragma unroll
        for (int j = 0; j < 4; j++) { ar[i][j] = 0.f; az[i][j] = 0.f; an[i][j] = 0.f; }

    if (t > 0) {
        for (int k0 = 0; k0 < HH; k0 += 16) {
            #pragma unroll
            for (int i = 0; i < 4; i++) {
                const int e = tid + i * 256;
                const int kk = e & 15, mm = e >> 4;
                As[kk][mm] = hprev[(size_t)mm * HH + k0 + kk];
            }
            #pragma unroll
            for (int g = 0; g < 3; g++) {
                #pragma unroll
                for (int i = 0; i < 4; i++) {
                    const int e = tid + i * 256;
                    const int kk = e & 15, nn = e >> 4;
                    Bs[g][kk][nn] = Whh[(size_t)(g * HH + n0 + nn) * HH + k0 + kk];
                }
            }
            __syncthreads();
            #pragma unroll
            for (int kk = 0; kk < 16; kk++) {
                float a[4];
                #pragma unroll
                for (int i = 0; i < 4; i++) a[i] = As[kk][ty * 4 + i];
                float br[4], bz[4], bn[4];
                #pragma unroll
                for (int j = 0; j < 4; j++) {
                    br[j] = Bs[0][kk][tx * 4 + j];
                    bz[j] = Bs[1][kk][tx * 4 + j];
                    bn[j] = Bs[2][kk][tx * 4 + j];
                }
                #pragma unroll
                for (int i = 0; i < 4; i++)
                    #pragma unroll
                    for (int j = 0; j < 4; j++) {
                        ar[i][j] += a[i] * br[j];
                        az[i][j] += a[i] * bz[j];
                        an[i][j] += a[i] * bn[j];
                    }
            }
            __syncthreads();
        }
    }

    #pragma unroll
    for (int i = 0; i < 4; i++) {
        const int m = ty * 4 + i;
        #pragma unroll
        for (int j = 0; j < 4; j++) {
            const int n = n0 + tx * 4 + j;
            const float gir = gi[(size_t)m * G3 + n];
            const float giz = gi[(size_t)m * G3 + HH + n];
            const float gin = gi[(size_t)m * G3 + 2 * HH + n];
            const float hp = (t > 0) ? hprev[(size_t)m * HH + n] : 0.f;
            const float r  = sigmoidf_(gir + ar[i][j] + bhh[n]);
            const float z  = sigmoidf_(giz + az[i][j] + bhh[HH + n]);
            const float nn2 = tanhf(gin + r * (an[i][j] + bhh[2 * HH + n]));
            hout[(size_t)m * HH + n] = (1.f - z) * nn2 + z * hp;
        }
    }
}

// ---------------------------------------------------------------------------
// Projection: emb[b,:] = concat(fwd_h_last[b], bwd_h_last[b]) [2H];
// out[z=0] = emb @ W_mu^T + b_mu, out[z=1] = emb @ W_lv^T + b_lv.
// ---------------------------------------------------------------------------
__global__ __launch_bounds__(256) void proj_kernel(
    const float* __restrict__ Wmu, const float* __restrict__ bmu,
    const float* __restrict__ Wlv, const float* __restrict__ blv,
    float* __restrict__ out)
{
    __shared__ float As[16][66];
    __shared__ float Bs[16][66];

    const int which = blockIdx.z;
    const float* W    = which ? Wlv : Wmu;
    const float* bias = which ? blv : bmu;
    const int n0 = blockIdx.x * 64;
    const int m0 = blockIdx.y * 64;

    const float* hf = &g_seq[0][((size_t)(TT - 1) * BB + m0) * HH];
    const float* hb = &g_seq[1][((size_t)(TT - 1) * BB + m0) * HH];

    const int tid = threadIdx.x;
    const int tx = tid & 15, ty = tid >> 4;

    float acc[4][4];
    #pragma unroll
    for (int i = 0; i < 4; i++)
        #pragma unroll
        for (int j = 0; j < 4; j++) acc[i][j] = 0.f;

    for (int k0 = 0; k0 < 2 * HH; k0 += 16) {
        #pragma unroll
        for (int i = 0; i < 4; i++) {
            const int e = tid + i * 256;
            const int kk = e & 15, mm = e >> 4;
            const int k = k0 + kk;
            As[kk][mm] = (k < HH) ? hf[(size_t)mm * HH + k]
                                  : hb[(size_t)mm * HH + (k - HH)];
            Bs[kk][mm] = W[(size_t)(n0 + mm) * (2 * HH) + k];
        }
        __syncthreads();
        #pragma unroll
        for (int kk = 0; kk < 16; kk++) {
            float a[4], b[4];
            #pragma unroll
            for (int i = 0; i < 4; i++) a[i] = As[kk][ty * 4 + i];
            #pragma unroll
            for (int j = 0; j < 4; j++) b[j] = Bs[kk][tx * 4 + j];
            #pragma unroll
            for (int i = 0; i < 4; i++)
                #pragma unroll
                for (int j = 0; j < 4; j++)
                    acc[i][j] += a[i] * b[j];
        }
        __syncthreads();
    }

    #pragma unroll
    for (int i = 0; i < 4; i++) {
        const int m = m0 + ty * 4 + i;
        #pragma unroll
        for (int j = 0; j < 4; j++) {
            const int n = n0 + tx * 4 + j;
            out[(size_t)which * BB * HH + (size_t)m * HH + n] = acc[i][j] + bias[n];
        }
    }
}

extern "C" void kernel_launch(void* const* d_in, const int* in_sizes, int n_in,
                              void* d_out, int out_size)
{
    (void)in_sizes; (void)n_in; (void)out_size;
    const float* x       = (const float*)d_in[0];
    // d_in[1] = batch_size (compile-time constant here)
    const float* fw_Wih0 = (const float*)d_in[2];
    const float* fw_Whh0 = (const float*)d_in[3];
    const float* fw_bih0 = (const float*)d_in[4];
    const float* fw_bhh0 = (const float*)d_in[5];
    const float* fw_Wih  = (const float*)d_in[6];
    const float* fw_Whh  = (const float*)d_in[7];
    const float* fw_bih  = (const float*)d_in[8];
    const float* fw_bhh  = (const float*)d_in[9];
    const float* bw_Wih0 = (const float*)d_in[10];
    const float* bw_Whh0 = (const float*)d_in[11];
    const float* bw_bih0 = (const float*)d_in[12];
    const float* bw_bhh0 = (const float*)d_in[13];
    const float* bw_Wih  = (const float*)d_in[14];
    const float* bw_Whh  = (const float*)d_in[15];
    const float* bw_bih  = (const float*)d_in[16];
    const float* bw_bhh  = (const float*)d_in[17];
    const float* W_mu    = (const float*)d_in[18];
    const float* b_mu    = (const float*)d_in[19];
    const float* W_lv    = (const float*)d_in[20];
    const float* b_lv    = (const float*)d_in[21];
    float* out = (float*)d_out;

    const dim3 ggi(G3 / 64, (TT * BB) / 64, 2);
    const dim3 gst(HH / 64, BB / 64, 2);

    // Layer 0: gi from raw input (dir 1 reads reversed time), then 128 steps.
    gi_gemm<<<ggi, 256>>>(x, DD, 1, fw_Wih0, bw_Wih0, fw_bih0, bw_bih0);
    for (int t = 0; t < TT; t++)
        gru_step<<<gst, 256>>>(t, fw_Whh0, bw_Whh0, fw_bhh0, bw_bhh0);

    // Layers 1..2: gi from previous layer's full sequence, then 128 steps.
    for (int l = 0; l < 2; l++) {
        gi_gemm<<<ggi, 256>>>(nullptr, HH, 0,
                              fw_Wih + (size_t)l * G3 * HH, bw_Wih + (size_t)l * G3 * HH,
                              fw_bih + (size_t)l * G3,      bw_bih + (size_t)l * G3);
        for (int t = 0; t < TT; t++)
            gru_step<<<gst, 256>>>(t,
                                   fw_Whh + (size_t)l * G3 * HH, bw_Whh + (size_t)l * G3 * HH,
                                   fw_bhh + (size_t)l * G3,      bw_bhh + (size_t)l * G3);
    }

    proj_kernel<<<dim3(HH / 64, BB / 64, 2), 256>>>(W_mu, b_mu, W_lv, b_lv, out);
}